// round 2
// baseline (speedup 1.0000x reference)
#include <cuda_runtime.h>
#include <math.h>

#define Bn 64
#define Cc 64
#define COo 64
#define Nn 400
#define Ll 24

// ---------------- device scratch ----------------
__device__ float g_f1t[Bn*Ll*Nn];        // [b,l,n]
__device__ float g_f2t[Bn*Cc*Ll];        // [b,c,l] (atomic, zeroed each launch)
__device__ float g_f1s[Bn*Nn*Ll];        // [b,n,l]
__device__ float g_f2s[Bn*Cc*Nn];        // [b,c,n]
__device__ float g_xin[Bn*COo*Nn*Ll];    // x_input [b,o,n,l]
__device__ float g_T0[Bn*Ll*Ll];         // softmax T (pre-transpose) [b,p,l]
__device__ float g_xT[Bn*Cc*Nn*Ll];      // x_TAt [b,c,n,q]
__device__ float g_tmpb[Bn*Nn*Cc];       // [b,n,c]
__device__ float g_slog[Bn*Nn*Nn];
__device__ float g_slo[Bn*Nn*Nn];
__device__ float g_smax[Bn*Nn];
__device__ float g_A2[Nn*Nn];
__device__ float g_Mc[Bn*Nn*2*Nn];       // [b][q][k*400+n]
__device__ float g_sdiag[Bn*Nn];
__device__ float g_Y[Bn*2*Nn*COo*Ll];    // [b][k][n][o][l]
__device__ float g_acc[Bn*Nn*COo*Ll];    // spatial_gcn [b][n][o*24+l]
__device__ float g_h[Bn*COo*Nn*Ll];      // pre-LN [b,o,n,l]
__device__ float g_bsum[Bn], g_bsq[Bn];

__global__ void kzero(){
  int i = blockIdx.x*256 + threadIdx.x;
  if(i < Bn*Cc*Ll) g_f2t[i] = 0.f;
  if(i < Bn){ g_bsum[i]=0.f; g_bsq[i]=0.f; }
}

__global__ void kA2(const float* __restrict__ adj){
  int p = blockIdx.x, t = threadIdx.x;  // 128 threads
  __shared__ float ar[Nn];
  for(int i=t;i<Nn;i+=128) ar[i] = adj[p*Nn+i];
  __syncthreads();
  for(int n2=t;n2<Nn;n2+=128){
    float s=0.f;
    for(int q=0;q<Nn;q++) s += ar[q]*adj[q*Nn+n2];
    g_A2[p*Nn+n2]=s;
  }
}

// fused conv1 + 4 attention feature reductions (one pass over x)
__global__ __launch_bounds__(384) void k1(const float* __restrict__ x,
    const float* __restrict__ w, const float* __restrict__ bias,
    const float* __restrict__ cw1t, const float* __restrict__ cw2t,
    const float* __restrict__ cw1s, const float* __restrict__ cw2s){
  __shared__ float Wsm[4096];
  __shared__ float redA[384], redB[384];
  int b = blockIdx.y, n0 = blockIdx.x*16;
  int t = threadIdx.x, nn = t/24, l = t%24, n = n0+nn;
  for(int i=t;i<4096;i+=384) Wsm[i]=w[i];
  __syncthreads();
  float acc[64];
#pragma unroll
  for(int o=0;o<64;o++) acc[o]=0.f;
  float s1t=0.f, s1s=0.f;
  float c2s_l = cw2s[l], c2t_n = cw2t[n];
  for(int c=0;c<64;c++){
    float val = x[((b*64+c)*Nn+n)*Ll+l];
    s1t += cw1t[c]*val;
    s1s += cw1s[c]*val;
    redA[t] = c2t_n*val;
    redB[t] = c2s_l*val;
#pragma unroll
    for(int o=0;o<64;o++) acc[o] += Wsm[o*64+c]*val;
    __syncthreads();
    if(t<24){ float s=0.f;
#pragma unroll
      for(int j=0;j<16;j++) s += redA[j*24+t];
      atomicAdd(&g_f2t[(b*64+c)*Ll+t], s);
    }
    if(l==0){ float s=0.f;
#pragma unroll
      for(int j=0;j<24;j++) s += redB[nn*24+j];
      g_f2s[(b*64+c)*Nn+n] = s;
    }
    __syncthreads();
  }
  g_f1t[(b*Ll+l)*Nn+n] = s1t;
  g_f1s[(b*Nn+n)*Ll+l] = s1s;
#pragma unroll
  for(int o=0;o<64;o++) g_xin[((b*64+o)*Nn+n)*Ll+l] = acc[o] + bias[o];
}

// temporal attention (one block per batch)
__global__ __launch_bounds__(256) void k2(const float* __restrict__ tw,
    const float* __restrict__ tb, const float* __restrict__ tv,
    float* __restrict__ Tout){
  int b = blockIdx.x, t = threadIdx.x;
  __shared__ float tmpa[24*64];
  __shared__ float f2sm[64*24];
  __shared__ float sig[576];
  __shared__ float lo[576];
  __shared__ float mcol[24], rsum[24];
  for(int i=t;i<1536;i+=256) f2sm[i] = g_f2t[b*1536+i];
  for(int i=t;i<1536;i+=256){
    int l=i/64, c=i%64;
    const float* f1 = &g_f1t[(b*Ll+l)*Nn];
    float s=0.f;
    for(int n=0;n<Nn;n++) s += f1[n]*tw[n*64+c];
    tmpa[i]=s;
  }
  __syncthreads();
  for(int i=t;i<576;i+=256){
    int l=i/24, l2=i%24;
    float s = tb[i];
#pragma unroll
    for(int c=0;c<64;c++) s += tmpa[l*64+c]*f2sm[c*24+l2];
    sig[i] = 1.f/(1.f+expf(-s));
  }
  __syncthreads();
  for(int i=t;i<576;i+=256){
    int p=i/24, l2=i%24;
    float s=0.f;
#pragma unroll
    for(int q=0;q<24;q++) s += tv[p*24+q]*sig[q*24+l2];
    lo[i]=s;
  }
  __syncthreads();
  if(t<24){ float m=-1e30f;
#pragma unroll
    for(int p=0;p<24;p++) m = fmaxf(m, lo[p*24+t]);
    mcol[t]=m;
  }
  __syncthreads();
  for(int i=t;i<576;i+=256) lo[i] = expf(lo[i]-mcol[i%24]);
  __syncthreads();
  if(t<24){ float s=0.f;
#pragma unroll
    for(int l2=0;l2<24;l2++) s += lo[t*24+l2];
    rsum[t]=s;
  }
  __syncthreads();
  for(int i=t;i<576;i+=256){
    int p=i/24, l2=i%24;
    float v = lo[i]/rsum[p];
    g_T0[b*576+i] = v;
    Tout[b*576 + l2*24 + p] = v;   // returned (swapped) T_coef
  }
}

// x_TAt[b,c,n,q] = sum_l x[b,c,n,l] * T0[b,q,l]
__global__ __launch_bounds__(256) void k3(const float* __restrict__ x){
  int b = blockIdx.y, c = blockIdx.x, t = threadIdx.x;
  __shared__ float T0t[576];     // [l][q]
  __shared__ float xs[9600];
  for(int i=t;i<576;i+=256){ int q=i/24, l=i%24; T0t[l*24+q] = g_T0[b*576+i]; }
  const float* xb = &x[(b*64+c)*9600];
  for(int i=t;i<9600;i+=256) xs[i]=xb[i];
  __syncthreads();
  float* outb = &g_xT[(b*64+c)*9600];
  for(int idx=t; idx<9600; idx+=256){
    int n=idx/24, q=idx%24;
    float s=0.f;
#pragma unroll
    for(int l=0;l<24;l++) s += xs[n*24+l]*T0t[l*24+q];
    outb[idx]=s;
  }
}

__global__ __launch_bounds__(256) void k4a(const float* __restrict__ sw){
  int b=blockIdx.x, t=threadIdx.x;
  __shared__ float sws[24*64];
  for(int i=t;i<1536;i+=256) sws[i]=sw[i];
  __syncthreads();
  for(int i=t;i<25600;i+=256){
    int n=i/64, c=i%64;
    const float* f1=&g_f1s[(b*Nn+n)*Ll];
    float s=0.f;
#pragma unroll
    for(int l=0;l<24;l++) s += f1[l]*sws[l*64+c];
    g_tmpb[b*25600+i]=s;
  }
}

// slog = sigmoid(tmpb @ f2s + s_b)
__global__ __launch_bounds__(256) void k4b(const float* __restrict__ sb){
  int b=blockIdx.z, m0=blockIdx.y*64, n0=blockIdx.x*64;
  __shared__ float As[16][68];
  __shared__ float Bs2[16][64];
  int t=threadIdx.x, tx=t&15, ty=t>>4;
  float acc[4][4];
#pragma unroll
  for(int i=0;i<4;i++)
#pragma unroll
    for(int j=0;j<4;j++) acc[i][j]=0.f;
  for(int k0=0;k0<64;k0+=16){
    for(int i=t;i<1024;i+=256){ int m=i>>4, kk=i&15; int gm=m0+m;
      As[kk][m] = (gm<Nn)? g_tmpb[(b*Nn+gm)*64 + k0+kk] : 0.f; }
    for(int i=t;i<1024;i+=256){ int kk=i>>6, nn=i&63; int gn=n0+nn;
      Bs2[kk][nn] = (gn<Nn)? g_f2s[(b*64+k0+kk)*Nn + gn] : 0.f; }
    __syncthreads();
#pragma unroll
    for(int kk=0;kk<16;kk++){
      float a[4], bb[4];
#pragma unroll
      for(int i=0;i<4;i++) a[i]=As[kk][ty+16*i];
#pragma unroll
      for(int j=0;j<4;j++) bb[j]=Bs2[kk][tx+16*j];
#pragma unroll
      for(int i=0;i<4;i++)
#pragma unroll
        for(int j=0;j<4;j++) acc[i][j] += a[i]*bb[j];
    }
    __syncthreads();
  }
#pragma unroll
  for(int i=0;i<4;i++){ int gm=m0+ty+16*i; if(gm>=Nn) continue;
#pragma unroll
    for(int j=0;j<4;j++){ int gn=n0+tx+16*j; if(gn>=Nn) continue;
      float v = acc[i][j] + sb[gm*Nn+gn];
      g_slog[((size_t)b*Nn+gm)*Nn+gn] = 1.f/(1.f+expf(-v));
    } }
}

// slo = s_v @ slog
__global__ __launch_bounds__(256) void k4c(const float* __restrict__ sv){
  int b=blockIdx.z, m0=blockIdx.y*64, n0=blockIdx.x*64;
  const float* Bm=&g_slog[(size_t)b*160000];
  float* Cm=&g_slo[(size_t)b*160000];
  __shared__ float As[16][68];
  __shared__ float Bs2[16][64];
  int t=threadIdx.x, tx=t&15, ty=t>>4;
  float acc[4][4];
#pragma unroll
  for(int i=0;i<4;i++)
#pragma unroll
    for(int j=0;j<4;j++) acc[i][j]=0.f;
  for(int k0=0;k0<Nn;k0+=16){
    for(int i=t;i<1024;i+=256){ int m=i>>4, kk=i&15; int gm=m0+m;
      As[kk][m] = (gm<Nn)? sv[gm*Nn + k0+kk] : 0.f; }
    for(int i=t;i<1024;i+=256){ int kk=i>>6, nn=i&63; int gn=n0+nn;
      Bs2[kk][nn] = (gn<Nn)? Bm[(k0+kk)*Nn + gn] : 0.f; }
    __syncthreads();
#pragma unroll
    for(int kk=0;kk<16;kk++){
      float a[4], bb[4];
#pragma unroll
      for(int i=0;i<4;i++) a[i]=As[kk][ty+16*i];
#pragma unroll
      for(int j=0;j<4;j++) bb[j]=Bs2[kk][tx+16*j];
#pragma unroll
      for(int i=0;i<4;i++)
#pragma unroll
        for(int j=0;j<4;j++) acc[i][j] += a[i]*bb[j];
    }
    __syncthreads();
  }
#pragma unroll
  for(int i=0;i<4;i++){ int gm=m0+ty+16*i; if(gm>=Nn) continue;
#pragma unroll
    for(int j=0;j<4;j++){ int gn=n0+tx+16*j; if(gn>=Nn) continue;
      Cm[gm*Nn+gn] = acc[i][j];
    } }
}

__global__ void k4d(){
  int b=blockIdx.y;
  int n2=blockIdx.x*256+threadIdx.x;
  if(n2<Nn){
    float m=-1e30f;
    const float* p=&g_slo[(size_t)b*160000+n2];
    for(int q=0;q<Nn;q++) m=fmaxf(m, p[q*Nn]);
    g_smax[b*Nn+n2]=m;
  }
}

// softmax rows -> S_coef out + Mcat + diag
__global__ __launch_bounds__(128) void k4e(const float* __restrict__ adj, float* __restrict__ Sout){
  int b=blockIdx.y, p=blockIdx.x, t=threadIdx.x;
  __shared__ float e[Nn];
  __shared__ float red[128];
  const float* row=&g_slo[((size_t)b*Nn+p)*Nn];
  const float* mx=&g_smax[b*Nn];
  float ls=0.f;
  for(int i=t;i<Nn;i+=128){ float v=expf(row[i]-mx[i]); e[i]=v; ls+=v; }
  red[t]=ls; __syncthreads();
  for(int s=64;s>0;s>>=1){ if(t<s) red[t]+=red[t+s]; __syncthreads(); }
  float inv=1.f/red[0];
  for(int i=t;i<Nn;i+=128){
    float S = e[i]*inv;
    Sout[((size_t)b*Nn+p)*Nn+i] = S;
    g_Mc[((size_t)b*Nn+p)*800 + i]      = S*adj[p*Nn+i];
    g_Mc[((size_t)b*Nn+p)*800 + Nn + i] = S*(2.f*g_A2[p*Nn+i] - ((i==p)?1.f:0.f));
    if(i==p) g_sdiag[b*Nn+p]=S;
  }
}

// y_k = g_w[:, c*3+k] proj of x_TAt; k=0 applies diag(S) into g_acc
__global__ __launch_bounds__(384) void k5(const float* __restrict__ gw, int k){
  __shared__ float Wsm[4096];
  int b=blockIdx.y, n0=blockIdx.x*16;
  int t=threadIdx.x, nn=t/24, l=t%24, n=n0+nn;
  for(int i=t;i<4096;i+=384){ int o=i>>6, c=i&63; Wsm[i]=gw[o*192 + c*3 + k]; }
  __syncthreads();
  float acc[64];
#pragma unroll
  for(int o=0;o<64;o++) acc[o]=0.f;
  for(int c=0;c<64;c++){
    float val = g_xT[((b*64+c)*Nn+n)*Ll+l];
#pragma unroll
    for(int o=0;o<64;o++) acc[o] += Wsm[o*64+c]*val;
  }
  if(k==0){
    float d=g_sdiag[b*Nn+n];
#pragma unroll
    for(int o=0;o<64;o++) g_acc[(((size_t)b*Nn+n)*64+o)*Ll+l] = d*acc[o];
  } else {
    size_t base = (((size_t)(b*2+(k-1))*Nn+n)*64)*Ll + l;
#pragma unroll
    for(int o=0;o<64;o++) g_Y[base + (size_t)o*Ll] = acc[o];
  }
}

// big SGEMM: g_acc = relu(g_acc + Mcat @ Y + g_b[o])
__global__ __launch_bounds__(256) void k6(const float* __restrict__ gb){
  int b=blockIdx.z, m0=blockIdx.y*128, n0=blockIdx.x*128;
  const float* A  = g_Mc + (size_t)b*320000;
  const float* Bm = g_Y  + (size_t)b*1228800;
  float* Cm       = g_acc+ (size_t)b*614400;
  __shared__ float As[8][132];
  __shared__ float Bs2[8][128];
  int t=threadIdx.x, tx=t&15, ty=t>>4;
  float acc[8][8];
#pragma unroll
  for(int i=0;i<8;i++)
#pragma unroll
    for(int j=0;j<8;j++) acc[i][j]=0.f;
  for(int k0=0;k0<800;k0+=8){
    for(int i=t;i<1024;i+=256){ int m=i>>3, kk=i&7; int gm=m0+m;
      As[kk][m] = (gm<Nn)? A[gm*800 + k0+kk] : 0.f; }
    for(int i=t;i<1024;i+=256){ int kk=i>>7, nn=i&127;
      Bs2[kk][nn] = Bm[(size_t)(k0+kk)*1536 + n0+nn]; }
    __syncthreads();
#pragma unroll
    for(int kk=0;kk<8;kk++){
      float a[8], bb[8];
#pragma unroll
      for(int i=0;i<8;i++) a[i]=As[kk][ty+16*i];
#pragma unroll
      for(int j=0;j<8;j++) bb[j]=Bs2[kk][tx+16*j];
#pragma unroll
      for(int i=0;i<8;i++)
#pragma unroll
        for(int j=0;j<8;j++) acc[i][j] += a[i]*bb[j];
    }
    __syncthreads();
  }
#pragma unroll
  for(int i=0;i<8;i++){ int gm=m0+ty+16*i; if(gm>=Nn) continue;
#pragma unroll
    for(int j=0;j<8;j++){ int gn=n0+tx+16*j; int o=gn/24;
      size_t ci=(size_t)gm*1536+gn;
      float v = Cm[ci] + acc[i][j] + gb[o];
      Cm[ci] = fmaxf(v, 0.f);
    } }
}

// temporal conv + residual + relu + LN partial sums
__global__ __launch_bounds__(256) void k7(const float* __restrict__ tcw, const float* __restrict__ tcb){
  __shared__ float sgs[4*64*28];
  __shared__ float wsm[8], wsq[8];
  int b=blockIdx.y, n0=blockIdx.x*4;
  int t=threadIdx.x;
  for(int i=t;i<6144;i+=256){
    int nn=i/1536, r=i%1536, ii=r/24, l=r%24;
    sgs[(nn*64+ii)*28 + 1 + l] = g_acc[(((size_t)b*Nn + n0+nn)*64 + ii)*Ll + l];
  }
  { int nn=t>>6, ii=t&63; sgs[(nn*64+ii)*28+0]=0.f; sgs[(nn*64+ii)*28+25]=0.f; }
  __syncthreads();
  int nn=t>>6, o=t&63, n=n0+nn;
  float hv[24];
#pragma unroll
  for(int l=0;l<24;l++) hv[l]=tcb[o];
  for(int i=0;i<64;i++){
    float w0=__ldg(&tcw[(o*64+i)*3+0]);
    float w1=__ldg(&tcw[(o*64+i)*3+1]);
    float w2=__ldg(&tcw[(o*64+i)*3+2]);
    const float* r=&sgs[(nn*64+i)*28];
    float rv[26];
#pragma unroll
    for(int l=0;l<26;l++) rv[l]=r[l];
#pragma unroll
    for(int l=0;l<24;l++) hv[l] += w0*rv[l] + w1*rv[l+1] + w2*rv[l+2];
  }
  const float* xin=&g_xin[((b*64+o)*Nn+n)*Ll];
  float* hp=&g_h[((b*64+o)*Nn+n)*Ll];
  float ssum=0.f, ssq=0.f;
#pragma unroll
  for(int l=0;l<24;l++){
    float v=hv[l]+xin[l];
    v=fmaxf(v,0.f);
    hp[l]=v; ssum+=v; ssq+=v*v;
  }
  for(int off=16;off;off>>=1){
    ssum += __shfl_down_sync(0xffffffffu, ssum, off);
    ssq  += __shfl_down_sync(0xffffffffu, ssq , off);
  }
  if((t&31)==0){ wsm[t>>5]=ssum; wsq[t>>5]=ssq; }
  __syncthreads();
  if(t==0){
    float a=0.f, q=0.f;
#pragma unroll
    for(int i=0;i<8;i++){ a+=wsm[i]; q+=wsq[i]; }
    atomicAdd(&g_bsum[b], a);
    atomicAdd(&g_bsq[b], q);
  }
}

// LayerNorm finalize
__global__ void k8(const float* __restrict__ lg, const float* __restrict__ lb,
                   float* __restrict__ out){
  int b=blockIdx.y;
  size_t base=(size_t)b*614400;
  const float invc = 1.f/614400.f;
  float mu=g_bsum[b]*invc;
  float var=g_bsq[b]*invc - mu*mu;
  float rs=rsqrtf(var+1e-5f);
  for(int i=blockIdx.x*256+threadIdx.x; i<614400; i+=gridDim.x*256){
    out[base+i]=(g_h[base+i]-mu)*rs*lg[i]+lb[i];
  }
}

extern "C" void kernel_launch(void* const* d_in, const int* in_sizes, int n_in,
                              void* d_out, int out_size) {
  const float* x    = (const float*)d_in[0];
  const float* sup  = (const float*)d_in[1];
  const float* c1w  = (const float*)d_in[2];
  const float* c1b  = (const float*)d_in[3];
  const float* tcw1 = (const float*)d_in[4];
  const float* tcw2 = (const float*)d_in[5];
  const float* tw   = (const float*)d_in[6];
  const float* tb   = (const float*)d_in[7];
  const float* tv   = (const float*)d_in[8];
  const float* scw1 = (const float*)d_in[9];
  const float* scw2 = (const float*)d_in[10];
  const float* sw   = (const float*)d_in[11];
  const float* sb   = (const float*)d_in[12];
  const float* sv   = (const float*)d_in[13];
  const float* gw   = (const float*)d_in[14];
  const float* gb   = (const float*)d_in[15];
  const float* tcw  = (const float*)d_in[16];
  const float* tcb  = (const float*)d_in[17];
  const float* lng  = (const float*)d_in[18];
  const float* lnb  = (const float*)d_in[19];

  float* out  = (float*)d_out;                       // [64,64,400,24]
  float* Sout = out + (size_t)Bn*COo*Nn*Ll;          // [64,400,400]
  float* Tout = Sout + (size_t)Bn*Nn*Nn;             // [64,24,24]

  kzero<<<384,256>>>();
  kA2<<<Nn,128>>>(sup);
  k1<<<dim3(25,Bn),384>>>(x, c1w, c1b, tcw1, tcw2, scw1, scw2);
  k2<<<Bn,256>>>(tw, tb, tv, Tout);
  k3<<<dim3(Cc,Bn),256>>>(x);
  k4a<<<Bn,256>>>(sw);
  k4b<<<dim3(7,7,Bn),256>>>(sb);
  k4c<<<dim3(7,7,Bn),256>>>(sv);
  k4d<<<dim3(2,Bn),256>>>();
  k4e<<<dim3(Nn,Bn),128>>>(sup, Sout);
  k5<<<dim3(25,Bn),384>>>(gw, 0);
  k5<<<dim3(25,Bn),384>>>(gw, 1);
  k5<<<dim3(25,Bn),384>>>(gw, 2);
  k6<<<dim3(12,4,Bn),256>>>(gb);
  k7<<<dim3(100,Bn),256>>>(tcw, tcb);
  k8<<<dim3(300,Bn),256>>>(lng, lnb, out);
}

// round 3
// speedup vs baseline: 1.1673x; 1.1673x over previous
#include <cuda_runtime.h>
#include <math.h>

#define Bn 64
#define Cc 64
#define COo 64
#define Nn 400
#define Ll 24

typedef unsigned long long u64;
__device__ __forceinline__ u64 pk2(float lo, float hi){ u64 r; asm("mov.b64 %0, {%1,%2};" : "=l"(r) : "f"(lo), "f"(hi)); return r; }
__device__ __forceinline__ void upk2(u64 v, float& lo, float& hi){ asm("mov.b64 {%0,%1}, %2;" : "=f"(lo), "=f"(hi) : "l"(v)); }
__device__ __forceinline__ u64 fma2(u64 a, u64 b, u64 c){ u64 d; asm("fma.rn.f32x2 %0, %1, %2, %3;" : "=l"(d) : "l"(a), "l"(b), "l"(c)); return d; }

// ---------------- device scratch ----------------
__device__ __align__(16) float g_f1t[Bn*Ll*Nn];        // [b,l,n]
__device__ __align__(16) float g_f2t[Bn*Cc*Ll];        // [b,c,l]
__device__ __align__(16) float g_f1s[Bn*Nn*Ll];        // [b,n,l]
__device__ __align__(16) float g_f2s[Bn*Cc*Nn];        // [b,c,n]
__device__ __align__(16) float g_xin[Bn*COo*Nn*Ll];    // x_input [b,o,nl]
__device__ __align__(16) float g_T0[Bn*Ll*Ll];         // softmax T [b,p,l]
__device__ __align__(16) float g_xT[Bn*Cc*Nn*Ll];      // x_TAt [b,c,nl]
__device__ __align__(16) float g_tmpb[Bn*Nn*Cc];       // [b,n,c]
__device__ __align__(16) float g_slog[Bn*Nn*Nn];
__device__ __align__(16) float g_slo[Bn*Nn*Nn];
__device__ __align__(16) float g_smax[Bn*Nn];
__device__ __align__(16) float g_A2[Nn*Nn];
__device__ __align__(16) float g_Mc[Bn*Nn*2*Nn];       // [b][q][k*400+n]
__device__ __align__(16) float g_sdiag[Bn*Nn];
__device__ __align__(16) float g_Y[Bn*2*Nn*COo*Ll];    // [b][k][n][o*24+l]
__device__ __align__(16) float g_acc[Bn*Nn*COo*Ll];    // [b][n][o*24+l]
__device__ __align__(16) float g_h[Bn*COo*Nn*Ll];      // [b,o,nl]
__device__ float g_bsum[Bn], g_bsq[Bn];

__global__ void kzero(){
  int i = threadIdx.x;
  if(i < Bn){ g_bsum[i]=0.f; g_bsq[i]=0.f; }
}

__global__ void kA2(const float* __restrict__ adj){
  int p = blockIdx.x, t = threadIdx.x;  // 128 threads
  __shared__ float ar[Nn];
  for(int i=t;i<Nn;i+=128) ar[i] = adj[p*Nn+i];
  __syncthreads();
  for(int n2=t;n2<Nn;n2+=128){
    float s=0.f;
    for(int q=0;q<Nn;q++) s += ar[q]*adj[q*Nn+n2];
    g_A2[p*Nn+n2]=s;
  }
}

// conv1 as SGEMM: g_xin[b][o][nl] = c1w[o][c] @ x[b][c][nl] + c1b
__global__ __launch_bounds__(128) void k1g(const float* __restrict__ x,
    const float* __restrict__ w, const float* __restrict__ bias){
  int b=blockIdx.y, nl0=blockIdx.x*128;
  const float* Xb = x + (size_t)b*614400;
  __shared__ u64 AsD[8][64];
  __shared__ u64 BsP[8][64];
  int t=threadIdx.x, tx=t&15, ty=t>>4;   // ty 0..7
  u64 acc2[8][4];
#pragma unroll
  for(int i=0;i<8;i++)
#pragma unroll
    for(int j=0;j<4;j++) acc2[i][j]=0ull;
  for(int k0=0;k0<64;k0+=8){
    for(int i=t;i<512;i+=128){ int o=i>>3, kk=i&7;
      float v=w[o*64 + k0+kk]; AsD[kk][o]=pk2(v,v); }
    for(int i=t;i<512;i+=128){ int kk=i>>6, p=i&63;
      BsP[kk][p]=*(const u64*)&Xb[(size_t)(k0+kk)*9600 + nl0 + 2*p]; }
    __syncthreads();
#pragma unroll
    for(int kk=0;kk<8;kk++){
      u64 a[8], bb[4];
#pragma unroll
      for(int i=0;i<8;i++) a[i]=AsD[kk][ty*8+i];
#pragma unroll
      for(int j=0;j<4;j++) bb[j]=BsP[kk][tx*4+j];
#pragma unroll
      for(int i=0;i<8;i++)
#pragma unroll
        for(int j=0;j<4;j++) acc2[i][j]=fma2(a[i],bb[j],acc2[i][j]);
    }
    __syncthreads();
  }
#pragma unroll
  for(int i=0;i<8;i++){ int o=ty*8+i; float bo=bias[o];
#pragma unroll
    for(int j=0;j<4;j++){ int nl=nl0+tx*8+2*j;
      float lo,hi; upk2(acc2[i][j],lo,hi);
      *(float2*)&g_xin[(size_t)(b*64+o)*9600 + nl] = make_float2(lo+bo, hi+bo);
    } }
}

// f2t[b,c,l] = sum_n cw2t[n]*x ; f2s[b,c,n] = sum_l cw2s[l]*x
__global__ __launch_bounds__(256) void kB(const float* __restrict__ x,
    const float* __restrict__ cw2t, const float* __restrict__ cw2s){
  int b=blockIdx.y, c=blockIdx.x, t=threadIdx.x;
  __shared__ float xs[9600];
  const float* xb = &x[(size_t)(b*64+c)*9600];
  for(int i=t;i<9600;i+=256) xs[i]=xb[i];
  __syncthreads();
  for(int n=t;n<Nn;n+=256){
    float s=0.f;
#pragma unroll
    for(int l=0;l<24;l++) s += cw2s[l]*xs[n*24+l];
    g_f2s[(b*64+c)*Nn+n]=s;
  }
  if(t<24){
    float s=0.f;
    for(int n=0;n<Nn;n++) s += cw2t[n]*xs[n*24+t];
    g_f2t[(b*64+c)*Ll+t]=s;
  }
}

// f1t[b,l,n], f1s[b,n,l]: dot over c
__global__ __launch_bounds__(384) void kC(const float* __restrict__ x,
    const float* __restrict__ cw1t, const float* __restrict__ cw1s){
  int b=blockIdx.y; int nl=blockIdx.x*384+threadIdx.x;
  __shared__ float w1t[64], w1s[64];
  if(threadIdx.x<64){ w1t[threadIdx.x]=cw1t[threadIdx.x]; w1s[threadIdx.x]=cw1s[threadIdx.x]; }
  __syncthreads();
  const float* xb=&x[(size_t)b*614400 + nl];
  float s1=0.f, s2=0.f;
#pragma unroll 8
  for(int c=0;c<64;c++){ float v=xb[(size_t)c*9600]; s1+=w1t[c]*v; s2+=w1s[c]*v; }
  int n=nl/24, l=nl%24;
  g_f1t[(b*Ll+l)*Nn+n]=s1;
  g_f1s[(b*Nn+n)*Ll+l]=s2;
}

// temporal attention (one block per batch)
__global__ __launch_bounds__(256) void k2(const float* __restrict__ tw,
    const float* __restrict__ tb, const float* __restrict__ tv,
    float* __restrict__ Tout){
  int b = blockIdx.x, t = threadIdx.x;
  __shared__ float tmpa[24*64];
  __shared__ float f2sm[64*24];
  __shared__ float sig[576];
  __shared__ float lo[576];
  __shared__ float mcol[24], rsum[24];
  for(int i=t;i<1536;i+=256) f2sm[i] = g_f2t[b*1536+i];
  for(int i=t;i<1536;i+=256){
    int l=i/64, c=i%64;
    const float* f1 = &g_f1t[(b*Ll+l)*Nn];
    float s=0.f;
    for(int n=0;n<Nn;n++) s += f1[n]*tw[n*64+c];
    tmpa[i]=s;
  }
  __syncthreads();
  for(int i=t;i<576;i+=256){
    int l=i/24, l2=i%24;
    float s = tb[i];
#pragma unroll
    for(int c=0;c<64;c++) s += tmpa[l*64+c]*f2sm[c*24+l2];
    sig[i] = 1.f/(1.f+expf(-s));
  }
  __syncthreads();
  for(int i=t;i<576;i+=256){
    int p=i/24, l2=i%24;
    float s=0.f;
#pragma unroll
    for(int q=0;q<24;q++) s += tv[p*24+q]*sig[q*24+l2];
    lo[i]=s;
  }
  __syncthreads();
  if(t<24){ float m=-1e30f;
#pragma unroll
    for(int p=0;p<24;p++) m = fmaxf(m, lo[p*24+t]);
    mcol[t]=m;
  }
  __syncthreads();
  for(int i=t;i<576;i+=256) lo[i] = expf(lo[i]-mcol[i%24]);
  __syncthreads();
  if(t<24){ float s=0.f;
#pragma unroll
    for(int l2=0;l2<24;l2++) s += lo[t*24+l2];
    rsum[t]=s;
  }
  __syncthreads();
  for(int i=t;i<576;i+=256){
    int p=i/24, l2=i%24;
    float v = lo[i]/rsum[p];
    g_T0[b*576+i] = v;
    Tout[b*576 + l2*24 + p] = v;
  }
}

// x_TAt[b,c,n,q] = sum_l x[b,c,n,l] * T0[b,q,l]
__global__ __launch_bounds__(256) void k3(const float* __restrict__ x){
  int b = blockIdx.y, c = blockIdx.x, t = threadIdx.x;
  __shared__ float T0t[576];     // [l][q]
  __shared__ float xs[9600];
  for(int i=t;i<576;i+=256){ int q=i/24, l=i%24; T0t[l*24+q] = g_T0[b*576+i]; }
  const float* xb = &x[(size_t)(b*64+c)*9600];
  for(int i=t;i<9600;i+=256) xs[i]=xb[i];
  __syncthreads();
  float* outb = &g_xT[(size_t)(b*64+c)*9600];
  for(int idx=t; idx<9600; idx+=256){
    int n=idx/24, q=idx%24;
    float s=0.f;
#pragma unroll
    for(int l=0;l<24;l++) s += xs[n*24+l]*T0t[l*24+q];
    outb[idx]=s;
  }
}

__global__ __launch_bounds__(256) void k4a(const float* __restrict__ sw){
  int b=blockIdx.x, t=threadIdx.x;
  __shared__ float sws[24*64];
  for(int i=t;i<1536;i+=256) sws[i]=sw[i];
  __syncthreads();
  for(int i=t;i<25600;i+=256){
    int n=i/64, c=i%64;
    const float* f1=&g_f1s[(b*Nn+n)*Ll];
    float s=0.f;
#pragma unroll
    for(int l=0;l<24;l++) s += f1[l]*sws[l*64+c];
    g_tmpb[b*25600+i]=s;
  }
}

// slog = sigmoid(tmpb @ f2s + s_b)
__global__ __launch_bounds__(256) void k4b(const float* __restrict__ sb){
  int b=blockIdx.z, m0=blockIdx.y*64, n0=blockIdx.x*64;
  __shared__ float As[16][68];
  __shared__ float Bs2[16][64];
  int t=threadIdx.x, tx=t&15, ty=t>>4;
  float acc[4][4];
#pragma unroll
  for(int i=0;i<4;i++)
#pragma unroll
    for(int j=0;j<4;j++) acc[i][j]=0.f;
  for(int k0=0;k0<64;k0+=16){
    for(int i=t;i<1024;i+=256){ int m=i>>4, kk=i&15; int gm=m0+m;
      As[kk][m] = (gm<Nn)? g_tmpb[(b*Nn+gm)*64 + k0+kk] : 0.f; }
    for(int i=t;i<1024;i+=256){ int kk=i>>6, nn=i&63; int gn=n0+nn;
      Bs2[kk][nn] = (gn<Nn)? g_f2s[(b*64+k0+kk)*Nn + gn] : 0.f; }
    __syncthreads();
#pragma unroll
    for(int kk=0;kk<16;kk++){
      float a[4], bb[4];
#pragma unroll
      for(int i=0;i<4;i++) a[i]=As[kk][ty+16*i];
#pragma unroll
      for(int j=0;j<4;j++) bb[j]=Bs2[kk][tx+16*j];
#pragma unroll
      for(int i=0;i<4;i++)
#pragma unroll
        for(int j=0;j<4;j++) acc[i][j] += a[i]*bb[j];
    }
    __syncthreads();
  }
#pragma unroll
  for(int i=0;i<4;i++){ int gm=m0+ty+16*i; if(gm>=Nn) continue;
#pragma unroll
    for(int j=0;j<4;j++){ int gn=n0+tx+16*j; if(gn>=Nn) continue;
      float v = acc[i][j] + sb[gm*Nn+gn];
      g_slog[((size_t)b*Nn+gm)*Nn+gn] = 1.f/(1.f+expf(-v));
    } }
}

// slo = s_v @ slog   (f32x2 GEMM, Mtile=112, Ntile=128, K=400)
__global__ __launch_bounds__(256) void k4c(const float* __restrict__ sv){
  int b=blockIdx.z, m0=blockIdx.y*112, n0=blockIdx.x*128;
  const float* Bm=&g_slog[(size_t)b*160000];
  float* Cm=&g_slo[(size_t)b*160000];
  __shared__ u64 AsD[8][112];
  __shared__ u64 BsP[8][64];
  int t=threadIdx.x, tx=t&15, ty=t>>4;   // ty 0..15
  u64 acc2[7][4];
#pragma unroll
  for(int i=0;i<7;i++)
#pragma unroll
    for(int j=0;j<4;j++) acc2[i][j]=0ull;
  for(int k0=0;k0<400;k0+=8){
    for(int i=t;i<896;i+=256){ int m=i>>3, kk=i&7; int gm=m0+m;
      float v=(gm<Nn)? sv[gm*Nn + k0+kk] : 0.f; AsD[kk][m]=pk2(v,v); }
    for(int i=t;i<512;i+=256){ int kk=i>>6, p=i&63; int gn=n0+2*p;
      u64 v;
      if(gn+1<Nn)      v=*(const u64*)&Bm[(size_t)(k0+kk)*Nn + gn];
      else if(gn<Nn)   v=pk2(Bm[(size_t)(k0+kk)*Nn + gn], 0.f);
      else             v=0ull;
      BsP[kk][p]=v; }
    __syncthreads();
#pragma unroll
    for(int kk=0;kk<8;kk++){
      u64 a[7], bb[4];
#pragma unroll
      for(int i=0;i<7;i++) a[i]=AsD[kk][ty*7+i];
#pragma unroll
      for(int j=0;j<4;j++) bb[j]=BsP[kk][tx*4+j];
#pragma unroll
      for(int i=0;i<7;i++)
#pragma unroll
        for(int j=0;j<4;j++) acc2[i][j]=fma2(a[i],bb[j],acc2[i][j]);
    }
    __syncthreads();
  }
#pragma unroll
  for(int i=0;i<7;i++){ int gm=m0+ty*7+i; if(gm>=Nn) continue;
#pragma unroll
    for(int j=0;j<4;j++){ int gn=n0+tx*8+2*j;
      float lo,hi; upk2(acc2[i][j],lo,hi);
      if(gn<Nn)   Cm[gm*Nn+gn]=lo;
      if(gn+1<Nn) Cm[gm*Nn+gn+1]=hi;
    } }
}

__global__ void k4d(){
  int b=blockIdx.y;
  int n2=blockIdx.x*256+threadIdx.x;
  if(n2<Nn){
    float m=-1e30f;
    const float* p=&g_slo[(size_t)b*160000+n2];
#pragma unroll 8
    for(int q=0;q<Nn;q++) m=fmaxf(m, p[q*Nn]);
    g_smax[b*Nn+n2]=m;
  }
}

// softmax rows -> S_coef out + Mcat + diag
__global__ __launch_bounds__(128) void k4e(const float* __restrict__ adj, float* __restrict__ Sout){
  int b=blockIdx.y, p=blockIdx.x, t=threadIdx.x;
  __shared__ float e[Nn];
  __shared__ float red[128];
  const float* row=&g_slo[((size_t)b*Nn+p)*Nn];
  const float* mx=&g_smax[b*Nn];
  float ls=0.f;
  for(int i=t;i<Nn;i+=128){ float v=expf(row[i]-mx[i]); e[i]=v; ls+=v; }
  red[t]=ls; __syncthreads();
  for(int s=64;s>0;s>>=1){ if(t<s) red[t]+=red[t+s]; __syncthreads(); }
  float inv=1.f/red[0];
  for(int i=t;i<Nn;i+=128){
    float S = e[i]*inv;
    Sout[((size_t)b*Nn+p)*Nn+i] = S;
    g_Mc[((size_t)b*Nn+p)*800 + i]      = S*adj[p*Nn+i];
    g_Mc[((size_t)b*Nn+p)*800 + Nn + i] = S*(2.f*g_A2[p*Nn+i] - ((i==p)?1.f:0.f));
    if(i==p) g_sdiag[b*Nn+p]=S;
  }
}

// y_k projection as SGEMM: [64o x 64c] @ xT[c][nl]; k=0 scaled by diag(S) into g_acc
__global__ __launch_bounds__(128) void k5(const float* __restrict__ gw, int kp){
  int b=blockIdx.y, nl0=blockIdx.x*128;
  const float* Xb = g_xT + (size_t)b*614400;
  __shared__ u64 AsD[8][64];
  __shared__ u64 BsP[8][64];
  int t=threadIdx.x, tx=t&15, ty=t>>4;   // ty 0..7
  u64 acc2[8][4];
#pragma unroll
  for(int i=0;i<8;i++)
#pragma unroll
    for(int j=0;j<4;j++) acc2[i][j]=0ull;
  for(int k0=0;k0<64;k0+=8){
    for(int i=t;i<512;i+=128){ int o=i>>3, kk=i&7;
      float v=gw[o*192 + (k0+kk)*3 + kp]; AsD[kk][o]=pk2(v,v); }
    for(int i=t;i<512;i+=128){ int kk=i>>6, p=i&63;
      BsP[kk][p]=*(const u64*)&Xb[(size_t)(k0+kk)*9600 + nl0 + 2*p]; }
    __syncthreads();
#pragma unroll
    for(int kk=0;kk<8;kk++){
      u64 a[8], bb[4];
#pragma unroll
      for(int i=0;i<8;i++) a[i]=AsD[kk][ty*8+i];
#pragma unroll
      for(int j=0;j<4;j++) bb[j]=BsP[kk][tx*4+j];
#pragma unroll
      for(int i=0;i<8;i++)
#pragma unroll
        for(int j=0;j<4;j++) acc2[i][j]=fma2(a[i],bb[j],acc2[i][j]);
    }
    __syncthreads();
  }
  if(kp==0){
#pragma unroll
    for(int i=0;i<8;i++){ int o=ty*8+i;
#pragma unroll
      for(int j=0;j<4;j++){ int nl=nl0+tx*8+2*j; int n=nl/24, l=nl%24;
        float lo,hi; upk2(acc2[i][j],lo,hi);
        float d=g_sdiag[b*Nn+n];
        *(float2*)&g_acc[(size_t)(b*Nn+n)*1536 + o*24+l] = make_float2(d*lo, d*hi);
      } }
  } else {
    size_t kbase = (size_t)(b*2+kp-1)*Nn;
#pragma unroll
    for(int i=0;i<8;i++){ int o=ty*8+i;
#pragma unroll
      for(int j=0;j<4;j++){ int nl=nl0+tx*8+2*j; int n=nl/24, l=nl%24;
        float lo,hi; upk2(acc2[i][j],lo,hi);
        *(float2*)&g_Y[(kbase+n)*1536 + o*24+l] = make_float2(lo, hi);
      } }
  }
}

// big SGEMM (f32x2): g_acc = relu(g_acc + Mcat[400x800] @ Y[800x1536] + g_b[o])
__global__ __launch_bounds__(256) void k6(const float* __restrict__ gb){
  int b=blockIdx.z, m0=blockIdx.y*112, n0=blockIdx.x*128;
  const float* A  = g_Mc + (size_t)b*320000;
  const float* Bm = g_Y  + (size_t)b*1228800;
  float* Cm       = g_acc+ (size_t)b*614400;
  __shared__ u64 AsD[8][112];
  __shared__ u64 BsP[8][64];
  int t=threadIdx.x, tx=t&15, ty=t>>4;   // ty 0..15
  u64 acc2[7][4];
#pragma unroll
  for(int i=0;i<7;i++)
#pragma unroll
    for(int j=0;j<4;j++) acc2[i][j]=0ull;
  for(int k0=0;k0<800;k0+=8){
    for(int i=t;i<896;i+=256){ int m=i>>3, kk=i&7; int gm=m0+m;
      float v=(gm<Nn)? A[gm*800 + k0+kk] : 0.f; AsD[kk][m]=pk2(v,v); }
    for(int i=t;i<512;i+=256){ int kk=i>>6, p=i&63;
      BsP[kk][p]=*(const u64*)&Bm[(size_t)(k0+kk)*1536 + n0 + 2*p]; }
    __syncthreads();
#pragma unroll
    for(int kk=0;kk<8;kk++){
      u64 a[7], bb[4];
#pragma unroll
      for(int i=0;i<7;i++) a[i]=AsD[kk][ty*7+i];
#pragma unroll
      for(int j=0;j<4;j++) bb[j]=BsP[kk][tx*4+j];
#pragma unroll
      for(int i=0;i<7;i++)
#pragma unroll
        for(int j=0;j<4;j++) acc2[i][j]=fma2(a[i],bb[j],acc2[i][j]);
    }
    __syncthreads();
  }
#pragma unroll
  for(int i=0;i<7;i++){ int gm=m0+ty*7+i; if(gm>=Nn) continue;
#pragma unroll
    for(int j=0;j<4;j++){ int gn=n0+tx*8+2*j; int o=gn/24;
      float lo,hi; upk2(acc2[i][j],lo,hi);
      float2 c = *(float2*)&Cm[(size_t)gm*1536+gn];
      float go = gb[o];
      float v0 = fmaxf(c.x + lo + go, 0.f);
      float v1 = fmaxf(c.y + hi + go, 0.f);
      *(float2*)&Cm[(size_t)gm*1536+gn] = make_float2(v0, v1);
    } }
}

// temporal conv + residual + relu + LN partial sums
__global__ __launch_bounds__(256) void k7(const float* __restrict__ tcw, const float* __restrict__ tcb){
  __shared__ float sgs[4*64*28];
  __shared__ float wsm[8], wsq[8];
  int b=blockIdx.y, n0=blockIdx.x*4;
  int t=threadIdx.x;
  for(int i=t;i<6144;i+=256){
    int nn=i/1536, r=i%1536, ii=r/24, l=r%24;
    sgs[(nn*64+ii)*28 + 1 + l] = g_acc[(size_t)(b*Nn + n0+nn)*1536 + ii*24 + l];
  }
  { int nn=t>>6, ii=t&63; sgs[(nn*64+ii)*28+0]=0.f; sgs[(nn*64+ii)*28+25]=0.f; }
  __syncthreads();
  int nn=t>>6, o=t&63, n=n0+nn;
  float hv[24];
#pragma unroll
  for(int l=0;l<24;l++) hv[l]=tcb[o];
  for(int i=0;i<64;i++){
    float w0=__ldg(&tcw[(o*64+i)*3+0]);
    float w1=__ldg(&tcw[(o*64+i)*3+1]);
    float w2=__ldg(&tcw[(o*64+i)*3+2]);
    const float* r=&sgs[(nn*64+i)*28];
    float rv[26];
#pragma unroll
    for(int l=0;l<26;l++) rv[l]=r[l];
#pragma unroll
    for(int l=0;l<24;l++) hv[l] += w0*rv[l] + w1*rv[l+1] + w2*rv[l+2];
  }
  const float* xin=&g_xin[(size_t)(b*64+o)*9600 + n*24];
  float* hp=&g_h[(size_t)(b*64+o)*9600 + n*24];
  float ssum=0.f, ssq=0.f;
#pragma unroll
  for(int l=0;l<24;l++){
    float v=hv[l]+xin[l];
    v=fmaxf(v,0.f);
    hp[l]=v; ssum+=v; ssq+=v*v;
  }
  for(int off=16;off;off>>=1){
    ssum += __shfl_down_sync(0xffffffffu, ssum, off);
    ssq  += __shfl_down_sync(0xffffffffu, ssq , off);
  }
  if((t&31)==0){ wsm[t>>5]=ssum; wsq[t>>5]=ssq; }
  __syncthreads();
  if(t==0){
    float a=0.f, q=0.f;
#pragma unroll
    for(int i=0;i<8;i++){ a+=wsm[i]; q+=wsq[i]; }
    atomicAdd(&g_bsum[b], a);
    atomicAdd(&g_bsq[b], q);
  }
}

// LayerNorm finalize
__global__ void k8(const float* __restrict__ lg, const float* __restrict__ lb,
                   float* __restrict__ out){
  int b=blockIdx.y;
  size_t base=(size_t)b*614400;
  const float invc = 1.f/614400.f;
  float mu=g_bsum[b]*invc;
  float var=g_bsq[b]*invc - mu*mu;
  float rs=rsqrtf(var+1e-5f);
  for(int i=blockIdx.x*256+threadIdx.x; i<614400; i+=gridDim.x*256){
    out[base+i]=(g_h[base+i]-mu)*rs*lg[i]+lb[i];
  }
}

extern "C" void kernel_launch(void* const* d_in, const int* in_sizes, int n_in,
                              void* d_out, int out_size) {
  const float* x    = (const float*)d_in[0];
  const float* sup  = (const float*)d_in[1];
  const float* c1w  = (const float*)d_in[2];
  const float* c1b  = (const float*)d_in[3];
  const float* tcw1 = (const float*)d_in[4];
  const float* tcw2 = (const float*)d_in[5];
  const float* tw   = (const float*)d_in[6];
  const float* tb   = (const float*)d_in[7];
  const float* tv   = (const float*)d_in[8];
  const float* scw1 = (const float*)d_in[9];
  const float* scw2 = (const float*)d_in[10];
  const float* sw   = (const float*)d_in[11];
  const float* sb   = (const float*)d_in[12];
  const float* sv   = (const float*)d_in[13];
  const float* gw   = (const float*)d_in[14];
  const float* gb   = (const float*)d_in[15];
  const float* tcw  = (const float*)d_in[16];
  const float* tcb  = (const float*)d_in[17];
  const float* lng  = (const float*)d_in[18];
  const float* lnb  = (const float*)d_in[19];

  float* out  = (float*)d_out;
  float* Sout = out + (size_t)Bn*COo*Nn*Ll;
  float* Tout = Sout + (size_t)Bn*Nn*Nn;

  kzero<<<1,128>>>();
  kA2<<<Nn,128>>>(sup);
  k1g<<<dim3(75,Bn),128>>>(x, c1w, c1b);
  kB<<<dim3(Cc,Bn),256>>>(x, tcw2, scw2);
  kC<<<dim3(25,Bn),384>>>(x, tcw1, scw1);
  k2<<<Bn,256>>>(tw, tb, tv, Tout);
  k3<<<dim3(Cc,Bn),256>>>(x);
  k4a<<<Bn,256>>>(sw);
  k4b<<<dim3(7,7,Bn),256>>>(sb);
  k4c<<<dim3(4,4,Bn),256>>>(sv);
  k4d<<<dim3(2,Bn),256>>>();
  k4e<<<dim3(Nn,Bn),128>>>(sup, Sout);
  k5<<<dim3(75,Bn),128>>>(gw, 0);
  k5<<<dim3(75,Bn),128>>>(gw, 1);
  k5<<<dim3(75,Bn),128>>>(gw, 2);
  k6<<<dim3(12,4,Bn),256>>>(gb);
  k7<<<dim3(100,Bn),256>>>(tcw, tcb);
  k8<<<dim3(300,Bn),256>>>(lng, lnb, out);
}

// round 4
// speedup vs baseline: 1.5599x; 1.3363x over previous
#include <cuda_runtime.h>
#include <math.h>

#define Bn 64
#define Cc 64
#define COo 64
#define Nn 400
#define Ll 24

typedef unsigned long long u64;
__device__ __forceinline__ u64 pk2(float lo, float hi){ u64 r; asm("mov.b64 %0, {%1,%2};" : "=l"(r) : "f"(lo), "f"(hi)); return r; }
__device__ __forceinline__ void upk2(u64 v, float& lo, float& hi){ asm("mov.b64 {%0,%1}, %2;" : "=f"(lo), "=f"(hi) : "l"(v)); }
__device__ __forceinline__ u64 fma2(u64 a, u64 b, u64 c){ u64 d; asm("fma.rn.f32x2 %0, %1, %2, %3;" : "=l"(d) : "l"(a), "l"(b), "l"(c)); return d; }

// ---------------- device scratch ----------------
__device__ __align__(16) float g_f1t[Bn*Ll*Nn];        // [b,l,n]
__device__ __align__(16) float g_f2t[Bn*Cc*Ll];        // [b,c,l]
__device__ __align__(16) float g_f1s[Bn*Nn*Ll];        // [b,n,l]
__device__ __align__(16) float g_f2s[Bn*Cc*Nn];        // [b,c,n]
__device__ __align__(16) float g_xin[Bn*COo*Nn*Ll];    // x_input [b,o,nl]
__device__ __align__(16) float g_T0[Bn*Ll*Ll];         // softmax T [b,p,l]
__device__ __align__(16) float g_xT[Bn*Cc*Nn*Ll];      // x_TAt [b,c,nl]
__device__ __align__(16) float g_tmpb[Bn*Nn*Cc];       // [b,n,c]
__device__ __align__(16) float g_slog[Bn*Nn*Nn];
__device__ __align__(16) float g_slo[Bn*Nn*Nn];
__device__ __align__(16) float g_smax[Bn*Nn];
__device__ __align__(16) float g_A2[Nn*Nn];
__device__ __align__(16) float g_Mc[Bn*Nn*2*Nn];       // [b][q][k*400+n]
__device__ __align__(16) float g_sdiag[Bn*Nn];
__device__ __align__(16) float g_Y[Bn*2*Nn*COo*Ll];    // [b][k][n][o*24+l]
__device__ __align__(16) float g_acc[Bn*Nn*COo*Ll];    // [b][n][o*24+l]
__device__ __align__(16) float g_h[Bn*COo*Nn*Ll];      // [b,o,nl]
__device__ float g_bsum[Bn], g_bsq[Bn];

__global__ void kzero(){
  int i = threadIdx.x;
  if(i < Bn){ g_bsum[i]=0.f; g_bsq[i]=0.f; }
}

__global__ void kA2(const float* __restrict__ adj){
  int p = blockIdx.x, t = threadIdx.x;  // 128 threads
  __shared__ float ar[Nn];
  for(int i=t;i<Nn;i+=128) ar[i] = adj[p*Nn+i];
  __syncthreads();
  for(int n2=t;n2<Nn;n2+=128){
    float s=0.f;
    for(int q=0;q<Nn;q++) s += ar[q]*adj[q*Nn+n2];
    g_A2[p*Nn+n2]=s;
  }
}

// conv1 as SGEMM: g_xin[b][o][nl] = c1w[o][c] @ x[b][c][nl] + c1b
__global__ __launch_bounds__(128) void k1g(const float* __restrict__ x,
    const float* __restrict__ w, const float* __restrict__ bias){
  int b=blockIdx.y, nl0=blockIdx.x*128;
  const float* Xb = x + (size_t)b*614400;
  __shared__ float AsS[8][65];
  __shared__ u64 BsP[8][64];
  int t=threadIdx.x, tx=t&15, ty=t>>4;   // ty 0..7
  u64 acc2[8][4];
#pragma unroll
  for(int i=0;i<8;i++)
#pragma unroll
    for(int j=0;j<4;j++) acc2[i][j]=0ull;
  for(int k0=0;k0<64;k0+=8){
    for(int i=t;i<512;i+=128){ int o=i>>3, kk=i&7;
      AsS[kk][o]=w[o*64 + k0+kk]; }
    for(int i=t;i<512;i+=128){ int kk=i>>6, p=i&63;
      BsP[kk][p]=*(const u64*)&Xb[(size_t)(k0+kk)*9600 + nl0 + 2*p]; }
    __syncthreads();
#pragma unroll
    for(int kk=0;kk<8;kk++){
      u64 a[8], bb[4];
#pragma unroll
      for(int i=0;i<8;i++){ float v=AsS[kk][ty*8+i]; a[i]=pk2(v,v); }
#pragma unroll
      for(int j=0;j<4;j++) bb[j]=BsP[kk][tx+16*j];
#pragma unroll
      for(int i=0;i<8;i++)
#pragma unroll
        for(int j=0;j<4;j++) acc2[i][j]=fma2(a[i],bb[j],acc2[i][j]);
    }
    __syncthreads();
  }
#pragma unroll
  for(int i=0;i<8;i++){ int o=ty*8+i; float bo=bias[o];
#pragma unroll
    for(int j=0;j<4;j++){ int nl=nl0+2*(tx+16*j);
      float lo,hi; upk2(acc2[i][j],lo,hi);
      *(float2*)&g_xin[(size_t)(b*64+o)*9600 + nl] = make_float2(lo+bo, hi+bo);
    } }
}

// f2t[b,c,l] = sum_n cw2t[n]*x ; f2s[b,c,n] = sum_l cw2s[l]*x
__global__ __launch_bounds__(256) void kB(const float* __restrict__ x,
    const float* __restrict__ cw2t, const float* __restrict__ cw2s){
  int b=blockIdx.y, c=blockIdx.x, t=threadIdx.x;
  __shared__ float xs[9600];
  __shared__ float red[240];
  const float* xb = &x[(size_t)(b*64+c)*9600];
  for(int i=t;i<9600;i+=256) xs[i]=xb[i];
  __syncthreads();
  for(int n=t;n<Nn;n+=256){
    float s=0.f;
#pragma unroll
    for(int l=0;l<24;l++) s += cw2s[l]*xs[n*24+l];
    g_f2s[(b*64+c)*Nn+n]=s;
  }
  if(t<240){
    int l=t%24, g=t/24;       // 10 groups
    float s=0.f;
    for(int n=g;n<Nn;n+=10) s += cw2t[n]*xs[n*24+l];
    red[t]=s;
  }
  __syncthreads();
  if(t<24){
    float s=0.f;
#pragma unroll
    for(int g=0;g<10;g++) s+=red[g*24+t];
    g_f2t[(b*64+c)*Ll+t]=s;
  }
}

// f1t[b,l,n], f1s[b,n,l]: dot over c
__global__ __launch_bounds__(384) void kC(const float* __restrict__ x,
    const float* __restrict__ cw1t, const float* __restrict__ cw1s){
  int b=blockIdx.y; int nl=blockIdx.x*384+threadIdx.x;
  __shared__ float w1t[64], w1s[64];
  if(threadIdx.x<64){ w1t[threadIdx.x]=cw1t[threadIdx.x]; w1s[threadIdx.x]=cw1s[threadIdx.x]; }
  __syncthreads();
  const float* xb=&x[(size_t)b*614400 + nl];
  float s1=0.f, s2=0.f;
#pragma unroll 8
  for(int c=0;c<64;c++){ float v=xb[(size_t)c*9600]; s1+=w1t[c]*v; s2+=w1s[c]*v; }
  int n=nl/24, l=nl%24;
  g_f1t[(b*Ll+l)*Nn+n]=s1;
  g_f1s[(b*Nn+n)*Ll+l]=s2;
}

// temporal attention (one block per batch)
__global__ __launch_bounds__(256) void k2(const float* __restrict__ tw,
    const float* __restrict__ tb, const float* __restrict__ tv,
    float* __restrict__ Tout){
  int b = blockIdx.x, t = threadIdx.x;
  __shared__ float tmpa[24*64];
  __shared__ float f2sm[64*24];
  __shared__ float sig[576];
  __shared__ float lo[576];
  __shared__ float mcol[24], rsum[24];
  for(int i=t;i<1536;i+=256) f2sm[i] = g_f2t[b*1536+i];
  for(int i=t;i<1536;i+=256){
    int l=i/64, c=i%64;
    const float* f1 = &g_f1t[(b*Ll+l)*Nn];
    float s=0.f;
    for(int n=0;n<Nn;n++) s += f1[n]*tw[n*64+c];
    tmpa[i]=s;
  }
  __syncthreads();
  for(int i=t;i<576;i+=256){
    int l=i/24, l2=i%24;
    float s = tb[i];
#pragma unroll
    for(int c=0;c<64;c++) s += tmpa[l*64+c]*f2sm[c*24+l2];
    sig[i] = 1.f/(1.f+expf(-s));
  }
  __syncthreads();
  for(int i=t;i<576;i+=256){
    int p=i/24, l2=i%24;
    float s=0.f;
#pragma unroll
    for(int q=0;q<24;q++) s += tv[p*24+q]*sig[q*24+l2];
    lo[i]=s;
  }
  __syncthreads();
  if(t<24){ float m=-1e30f;
#pragma unroll
    for(int p=0;p<24;p++) m = fmaxf(m, lo[p*24+t]);
    mcol[t]=m;
  }
  __syncthreads();
  for(int i=t;i<576;i+=256) lo[i] = expf(lo[i]-mcol[i%24]);
  __syncthreads();
  if(t<24){ float s=0.f;
#pragma unroll
    for(int l2=0;l2<24;l2++) s += lo[t*24+l2];
    rsum[t]=s;
  }
  __syncthreads();
  for(int i=t;i<576;i+=256){
    int p=i/24, l2=i%24;
    float v = lo[i]/rsum[p];
    g_T0[b*576+i] = v;
    Tout[b*576 + l2*24 + p] = v;
  }
}

// x_TAt[b,c,n,q] = sum_l x[b,c,n,l] * T0[b,q,l]
__global__ __launch_bounds__(256) void k3(const float* __restrict__ x){
  int b = blockIdx.y, c = blockIdx.x, t = threadIdx.x;
  __shared__ float T0t[576];     // [l][q]
  __shared__ float xs[9600];
  for(int i=t;i<576;i+=256){ int q=i/24, l=i%24; T0t[l*24+q] = g_T0[b*576+i]; }
  const float* xb = &x[(size_t)(b*64+c)*9600];
  for(int i=t;i<9600;i+=256) xs[i]=xb[i];
  __syncthreads();
  float* outb = &g_xT[(size_t)(b*64+c)*9600];
  for(int idx=t; idx<9600; idx+=256){
    int n=idx/24, q=idx%24;
    float s=0.f;
#pragma unroll
    for(int l=0;l<24;l++) s += xs[n*24+l]*T0t[l*24+q];
    outb[idx]=s;
  }
}

__global__ __launch_bounds__(256) void k4a(const float* __restrict__ sw){
  int b=blockIdx.x, t=threadIdx.x;
  __shared__ float sws[24*64];
  for(int i=t;i<1536;i+=256) sws[i]=sw[i];
  __syncthreads();
  for(int i=t;i<25600;i+=256){
    int n=i/64, c=i%64;
    const float* f1=&g_f1s[(b*Nn+n)*Ll];
    float s=0.f;
#pragma unroll
    for(int l=0;l<24;l++) s += f1[l]*sws[l*64+c];
    g_tmpb[b*25600+i]=s;
  }
}

// slog = sigmoid(tmpb @ f2s + s_b)
__global__ __launch_bounds__(256) void k4b(const float* __restrict__ sb){
  int b=blockIdx.z, m0=blockIdx.y*64, n0=blockIdx.x*64;
  __shared__ float As[16][68];
  __shared__ float Bs2[16][64];
  int t=threadIdx.x, tx=t&15, ty=t>>4;
  float acc[4][4];
#pragma unroll
  for(int i=0;i<4;i++)
#pragma unroll
    for(int j=0;j<4;j++) acc[i][j]=0.f;
  for(int k0=0;k0<64;k0+=16){
    for(int i=t;i<1024;i+=256){ int m=i>>4, kk=i&15; int gm=m0+m;
      As[kk][m] = (gm<Nn)? g_tmpb[(b*Nn+gm)*64 + k0+kk] : 0.f; }
    for(int i=t;i<1024;i+=256){ int kk=i>>6, nn=i&63; int gn=n0+nn;
      Bs2[kk][nn] = (gn<Nn)? g_f2s[(b*64+k0+kk)*Nn + gn] : 0.f; }
    __syncthreads();
#pragma unroll
    for(int kk=0;kk<16;kk++){
      float a[4], bb[4];
#pragma unroll
      for(int i=0;i<4;i++) a[i]=As[kk][ty+16*i];
#pragma unroll
      for(int j=0;j<4;j++) bb[j]=Bs2[kk][tx+16*j];
#pragma unroll
      for(int i=0;i<4;i++)
#pragma unroll
        for(int j=0;j<4;j++) acc[i][j] += a[i]*bb[j];
    }
    __syncthreads();
  }
#pragma unroll
  for(int i=0;i<4;i++){ int gm=m0+ty+16*i; if(gm>=Nn) continue;
#pragma unroll
    for(int j=0;j<4;j++){ int gn=n0+tx+16*j; if(gn>=Nn) continue;
      float v = acc[i][j] + sb[gm*Nn+gn];
      g_slog[((size_t)b*Nn+gm)*Nn+gn] = 1.f/(1.f+expf(-v));
    } }
}

// slo = s_v @ slog   (f32x2 GEMM, Mtile=112, Ntile=128, K=400)
__global__ __launch_bounds__(256) void k4c(const float* __restrict__ sv){
  int b=blockIdx.z, m0=blockIdx.y*112, n0=blockIdx.x*128;
  const float* Bm=&g_slog[(size_t)b*160000];
  float* Cm=&g_slo[(size_t)b*160000];
  __shared__ float AsS[16][114];
  __shared__ u64 BsP[16][64];
  int t=threadIdx.x, tx=t&15, ty=t>>4;   // ty 0..15
  u64 acc2[7][4];
#pragma unroll
  for(int i=0;i<7;i++)
#pragma unroll
    for(int j=0;j<4;j++) acc2[i][j]=0ull;
  for(int k0=0;k0<400;k0+=16){
    for(int i=t;i<1792;i+=256){ int m=i>>4, kk=i&15; int gm=m0+m;
      AsS[kk][m]=(gm<Nn)? sv[gm*Nn + k0+kk] : 0.f; }
    for(int i=t;i<1024;i+=256){ int kk=i>>6, p=i&63; int gn=n0+2*p;
      u64 v;
      if(gn+1<Nn)      v=*(const u64*)&Bm[(size_t)(k0+kk)*Nn + gn];
      else if(gn<Nn)   v=pk2(Bm[(size_t)(k0+kk)*Nn + gn], 0.f);
      else             v=0ull;
      BsP[kk][p]=v; }
    __syncthreads();
#pragma unroll
    for(int kk=0;kk<16;kk++){
      u64 a[7], bb[4];
#pragma unroll
      for(int i=0;i<7;i++){ float v=AsS[kk][ty*7+i]; a[i]=pk2(v,v); }
#pragma unroll
      for(int j=0;j<4;j++) bb[j]=BsP[kk][tx+16*j];
#pragma unroll
      for(int i=0;i<7;i++)
#pragma unroll
        for(int j=0;j<4;j++) acc2[i][j]=fma2(a[i],bb[j],acc2[i][j]);
    }
    __syncthreads();
  }
#pragma unroll
  for(int i=0;i<7;i++){ int gm=m0+ty*7+i; if(gm>=Nn) continue;
#pragma unroll
    for(int j=0;j<4;j++){ int gn=n0+2*(tx+16*j);
      float lo,hi; upk2(acc2[i][j],lo,hi);
      if(gn<Nn)   Cm[gm*Nn+gn]=lo;
      if(gn+1<Nn) Cm[gm*Nn+gn+1]=hi;
    } }
}

__global__ void k4d(){
  int b=blockIdx.y;
  int n2=blockIdx.x*256+threadIdx.x;
  if(n2<Nn){
    float m=-1e30f;
    const float* p=&g_slo[(size_t)b*160000+n2];
#pragma unroll 8
    for(int q=0;q<Nn;q++) m=fmaxf(m, p[q*Nn]);
    g_smax[b*Nn+n2]=m;
  }
}

// softmax rows -> S_coef out + Mcat + diag
__global__ __launch_bounds__(128) void k4e(const float* __restrict__ adj, float* __restrict__ Sout){
  int b=blockIdx.y, p=blockIdx.x, t=threadIdx.x;
  __shared__ float e[Nn];
  __shared__ float red[128];
  const float* row=&g_slo[((size_t)b*Nn+p)*Nn];
  const float* mx=&g_smax[b*Nn];
  float ls=0.f;
  for(int i=t;i<Nn;i+=128){ float v=expf(row[i]-mx[i]); e[i]=v; ls+=v; }
  red[t]=ls; __syncthreads();
  for(int s=64;s>0;s>>=1){ if(t<s) red[t]+=red[t+s]; __syncthreads(); }
  float inv=1.f/red[0];
  for(int i=t;i<Nn;i+=128){
    float S = e[i]*inv;
    Sout[((size_t)b*Nn+p)*Nn+i] = S;
    g_Mc[((size_t)b*Nn+p)*800 + i]      = S*adj[p*Nn+i];
    g_Mc[((size_t)b*Nn+p)*800 + Nn + i] = S*(2.f*g_A2[p*Nn+i] - ((i==p)?1.f:0.f));
    if(i==p) g_sdiag[b*Nn+p]=S;
  }
}

// y_k projection as SGEMM: [64o x 64c] @ xT[c][nl]; k=0 scaled by diag(S) into g_acc
__global__ __launch_bounds__(128) void k5(const float* __restrict__ gw, int kp){
  int b=blockIdx.y, nl0=blockIdx.x*128;
  const float* Xb = g_xT + (size_t)b*614400;
  __shared__ float AsS[8][65];
  __shared__ u64 BsP[8][64];
  int t=threadIdx.x, tx=t&15, ty=t>>4;   // ty 0..7
  u64 acc2[8][4];
#pragma unroll
  for(int i=0;i<8;i++)
#pragma unroll
    for(int j=0;j<4;j++) acc2[i][j]=0ull;
  for(int k0=0;k0<64;k0+=8){
    for(int i=t;i<512;i+=128){ int o=i>>3, kk=i&7;
      AsS[kk][o]=gw[o*192 + (k0+kk)*3 + kp]; }
    for(int i=t;i<512;i+=128){ int kk=i>>6, p=i&63;
      BsP[kk][p]=*(const u64*)&Xb[(size_t)(k0+kk)*9600 + nl0 + 2*p]; }
    __syncthreads();
#pragma unroll
    for(int kk=0;kk<8;kk++){
      u64 a[8], bb[4];
#pragma unroll
      for(int i=0;i<8;i++){ float v=AsS[kk][ty*8+i]; a[i]=pk2(v,v); }
#pragma unroll
      for(int j=0;j<4;j++) bb[j]=BsP[kk][tx+16*j];
#pragma unroll
      for(int i=0;i<8;i++)
#pragma unroll
        for(int j=0;j<4;j++) acc2[i][j]=fma2(a[i],bb[j],acc2[i][j]);
    }
    __syncthreads();
  }
  if(kp==0){
#pragma unroll
    for(int i=0;i<8;i++){ int o=ty*8+i;
#pragma unroll
      for(int j=0;j<4;j++){ int nl=nl0+2*(tx+16*j); int n=nl/24, l=nl%24;
        float lo,hi; upk2(acc2[i][j],lo,hi);
        float d=g_sdiag[b*Nn+n];
        *(float2*)&g_acc[(size_t)(b*Nn+n)*1536 + o*24+l] = make_float2(d*lo, d*hi);
      } }
  } else {
    size_t kbase = (size_t)(b*2+kp-1)*Nn;
#pragma unroll
    for(int i=0;i<8;i++){ int o=ty*8+i;
#pragma unroll
      for(int j=0;j<4;j++){ int nl=nl0+2*(tx+16*j); int n=nl/24, l=nl%24;
        float lo,hi; upk2(acc2[i][j],lo,hi);
        *(float2*)&g_Y[(kbase+n)*1536 + o*24+l] = make_float2(lo, hi);
      } }
  }
}

// big SGEMM (f32x2): g_acc = relu(g_acc + Mcat[400x800] @ Y[800x1536] + g_b[o])
__global__ __launch_bounds__(256) void k6(const float* __restrict__ gb){
  int b=blockIdx.z, m0=blockIdx.y*112, n0=blockIdx.x*128;
  const float* A  = g_Mc + (size_t)b*320000;
  const float* Bm = g_Y  + (size_t)b*1228800;
  float* Cm       = g_acc+ (size_t)b*614400;
  __shared__ float AsS[16][114];
  __shared__ u64 BsP[16][64];
  int t=threadIdx.x, tx=t&15, ty=t>>4;   // ty 0..15
  u64 acc2[7][4];
#pragma unroll
  for(int i=0;i<7;i++)
#pragma unroll
    for(int j=0;j<4;j++) acc2[i][j]=0ull;
  for(int k0=0;k0<800;k0+=16){
    for(int i=t;i<1792;i+=256){ int m=i>>4, kk=i&15; int gm=m0+m;
      AsS[kk][m]=(gm<Nn)? A[gm*800 + k0+kk] : 0.f; }
    for(int i=t;i<1024;i+=256){ int kk=i>>6, p=i&63;
      BsP[kk][p]=*(const u64*)&Bm[(size_t)(k0+kk)*1536 + n0 + 2*p]; }
    __syncthreads();
#pragma unroll
    for(int kk=0;kk<16;kk++){
      u64 a[7], bb[4];
#pragma unroll
      for(int i=0;i<7;i++){ float v=AsS[kk][ty*7+i]; a[i]=pk2(v,v); }
#pragma unroll
      for(int j=0;j<4;j++) bb[j]=BsP[kk][tx+16*j];
#pragma unroll
      for(int i=0;i<7;i++)
#pragma unroll
        for(int j=0;j<4;j++) acc2[i][j]=fma2(a[i],bb[j],acc2[i][j]);
    }
    __syncthreads();
  }
#pragma unroll
  for(int i=0;i<7;i++){ int gm=m0+ty*7+i; if(gm>=Nn) continue;
#pragma unroll
    for(int j=0;j<4;j++){ int gn=n0+2*(tx+16*j); int o=gn/24;
      float lo,hi; upk2(acc2[i][j],lo,hi);
      float2 c = *(float2*)&Cm[(size_t)gm*1536+gn];
      float go = gb[o];
      float v0 = fmaxf(c.x + lo + go, 0.f);
      float v1 = fmaxf(c.y + hi + go, 0.f);
      *(float2*)&Cm[(size_t)gm*1536+gn] = make_float2(v0, v1);
    } }
}

// temporal conv + residual + relu + LN partial sums
__global__ __launch_bounds__(256) void k7(const float* __restrict__ tcw, const float* __restrict__ tcb){
  __shared__ float sgs[4*64*28];
  __shared__ float wsm[8], wsq[8];
  int b=blockIdx.y, n0=blockIdx.x*4;
  int t=threadIdx.x;
  for(int i=t;i<6144;i+=256){
    int nn=i/1536, r=i%1536, ii=r/24, l=r%24;
    sgs[(nn*64+ii)*28 + 1 + l] = g_acc[(size_t)(b*Nn + n0+nn)*1536 + ii*24 + l];
  }
  { int nn=t>>6, ii=t&63; sgs[(nn*64+ii)*28+0]=0.f; sgs[(nn*64+ii)*28+25]=0.f; }
  __syncthreads();
  int nn=t>>6, o=t&63, n=n0+nn;
  float hv[24];
#pragma unroll
  for(int l=0;l<24;l++) hv[l]=tcb[o];
  for(int i=0;i<64;i++){
    float w0=__ldg(&tcw[(o*64+i)*3+0]);
    float w1=__ldg(&tcw[(o*64+i)*3+1]);
    float w2=__ldg(&tcw[(o*64+i)*3+2]);
    const float* r=&sgs[(nn*64+i)*28];
    float rv[26];
#pragma unroll
    for(int l=0;l<26;l++) rv[l]=r[l];
#pragma unroll
    for(int l=0;l<24;l++) hv[l] += w0*rv[l] + w1*rv[l+1] + w2*rv[l+2];
  }
  const float* xin=&g_xin[(size_t)(b*64+o)*9600 + n*24];
  float* hp=&g_h[(size_t)(b*64+o)*9600 + n*24];
  float ssum=0.f, ssq=0.f;
#pragma unroll
  for(int l=0;l<24;l++){
    float v=hv[l]+xin[l];
    v=fmaxf(v,0.f);
    hp[l]=v; ssum+=v; ssq+=v*v;
  }
  for(int off=16;off;off>>=1){
    ssum += __shfl_down_sync(0xffffffffu, ssum, off);
    ssq  += __shfl_down_sync(0xffffffffu, ssq , off);
  }
  if((t&31)==0){ wsm[t>>5]=ssum; wsq[t>>5]=ssq; }
  __syncthreads();
  if(t==0){
    float a=0.f, q=0.f;
#pragma unroll
    for(int i=0;i<8;i++){ a+=wsm[i]; q+=wsq[i]; }
    atomicAdd(&g_bsum[b], a);
    atomicAdd(&g_bsq[b], q);
  }
}

// LayerNorm finalize
__global__ void k8(const float* __restrict__ lg, const float* __restrict__ lb,
                   float* __restrict__ out){
  int b=blockIdx.y;
  size_t base=(size_t)b*614400;
  const float invc = 1.f/614400.f;
  float mu=g_bsum[b]*invc;
  float var=g_bsq[b]*invc - mu*mu;
  float rs=rsqrtf(var+1e-5f);
  for(int i=blockIdx.x*256+threadIdx.x; i<614400; i+=gridDim.x*256){
    out[base+i]=(g_h[base+i]-mu)*rs*lg[i]+lb[i];
  }
}

extern "C" void kernel_launch(void* const* d_in, const int* in_sizes, int n_in,
                              void* d_out, int out_size) {
  const float* x    = (const float*)d_in[0];
  const float* sup  = (const float*)d_in[1];
  const float* c1w  = (const float*)d_in[2];
  const float* c1b  = (const float*)d_in[3];
  const float* tcw1 = (const float*)d_in[4];
  const float* tcw2 = (const float*)d_in[5];
  const float* tw   = (const float*)d_in[6];
  const float* tb   = (const float*)d_in[7];
  const float* tv   = (const float*)d_in[8];
  const float* scw1 = (const float*)d_in[9];
  const float* scw2 = (const float*)d_in[10];
  const float* sw   = (const float*)d_in[11];
  const float* sb   = (const float*)d_in[12];
  const float* sv   = (const float*)d_in[13];
  const float* gw   = (const float*)d_in[14];
  const float* gb   = (const float*)d_in[15];
  const float* tcw  = (const float*)d_in[16];
  const float* tcb  = (const float*)d_in[17];
  const float* lng  = (const float*)d_in[18];
  const float* lnb  = (const float*)d_in[19];

  float* out  = (float*)d_out;
  float* Sout = out + (size_t)Bn*COo*Nn*Ll;
  float* Tout = Sout + (size_t)Bn*Nn*Nn;

  kzero<<<1,128>>>();
  kA2<<<Nn,128>>>(sup);
  k1g<<<dim3(75,Bn),128>>>(x, c1w, c1b);
  kB<<<dim3(Cc,Bn),256>>>(x, tcw2, scw2);
  kC<<<dim3(25,Bn),384>>>(x, tcw1, scw1);
  k2<<<Bn,256>>>(tw, tb, tv, Tout);
  k3<<<dim3(Cc,Bn),256>>>(x);
  k4a<<<Bn,256>>>(sw);
  k4b<<<dim3(7,7,Bn),256>>>(sb);
  k4c<<<dim3(4,4,Bn),256>>>(sv);
  k4d<<<dim3(2,Bn),256>>>();
  k4e<<<dim3(Nn,Bn),128>>>(sup, Sout);
  k5<<<dim3(75,Bn),128>>>(gw, 0);
  k5<<<dim3(75,Bn),128>>>(gw, 1);
  k5<<<dim3(75,Bn),128>>>(gw, 2);
  k6<<<dim3(12,4,Bn),256>>>(gb);
  k7<<<dim3(100,Bn),256>>>(tcw, tcb);
  k8<<<dim3(300,Bn),256>>>(lng, lnb, out);
}